// round 2
// baseline (speedup 1.0000x reference)
#include <cuda_runtime.h>
#include <cuda_bf16.h>

// Problem constants
constexpr int B = 4, C = 32, H = 720, W = 720;
constexpr int HW = H * W;              // 518400
constexpr int BHW = B * HW;            // 2073600
constexpr int KD = 9;                  // diagonal taps
constexpr int PAD = KD / 2;            // 4

// Scratch (no cudaMalloc allowed): channel-sum, diag-pooled, collapsed weights
__device__ float g_s[BHW];
__device__ float g_d[BHW];
__device__ float g_w2[C * 3];

// K0: W2[o,kh] = sum_i conv_w[o,i,kh,0]
__global__ void k_wsum(const float* __restrict__ cw) {
    int t = threadIdx.x;                // 0..95 -> (o, kh)
    if (t >= C * 3) return;
    int o = t / 3, kh = t % 3;
    float acc = 0.f;
    #pragma unroll
    for (int i = 0; i < C; i++) acc += cw[o * (C * 3) + i * 3 + kh];
    g_w2[t] = acc;
}

// K1: s[b,h,w] = sum_c x[b,c,h,w]  (float4 over w)
__global__ void k_csum(const float* __restrict__ x) {
    int idx = blockIdx.x * blockDim.x + threadIdx.x;   // over BHW/4
    if (idx >= BHW / 4) return;
    int base = idx * 4;
    int b = base / HW;
    int hw = base % HW;
    const float4* xp = reinterpret_cast<const float4*>(x + (size_t)b * C * HW + hw);
    float4 acc = make_float4(0.f, 0.f, 0.f, 0.f);
    #pragma unroll
    for (int c = 0; c < C; c++) {
        float4 v = __ldg(&xp[(size_t)c * (HW / 4)]);
        acc.x += v.x; acc.y += v.y; acc.z += v.z; acc.w += v.w;
    }
    reinterpret_cast<float4*>(g_s)[idx] = acc;
}

// K2: d[b,h,w] = (1/9) * sum_{j=-4..4} s[b, h+j, w+j]  (zero outside)
__global__ void k_diag() {
    int idx = blockIdx.x * blockDim.x + threadIdx.x;   // over BHW
    if (idx >= BHW) return;
    int b = idx / HW;
    int r = idx % HW;
    int h = r / W;
    int w = r % W;
    const float* sb = g_s + b * HW;
    float acc = 0.f;
    #pragma unroll
    for (int j = -PAD; j <= PAD; j++) {
        int hh = h + j, ww = w + j;
        if (hh >= 0 && hh < H && ww >= 0 && ww < W)
            acc += __ldg(&sb[hh * W + ww]);
    }
    g_d[idx] = acc * (1.0f / 9.0f);
}

// K3: out[b,o,h,w] = sum_kh W2[o,kh] * d[b, h-1+kh, w]  (float4 over w)
__global__ void k_conv(float* __restrict__ out) {
    __shared__ float sw[C * 3];
    if (threadIdx.x < C * 3) sw[threadIdx.x] = g_w2[threadIdx.x];
    __syncthreads();

    int idx = blockIdx.x * blockDim.x + threadIdx.x;   // over BHW/4
    if (idx >= BHW / 4) return;
    int base = idx * 4;
    int b = base / HW;
    int r = base % HW;
    int h = r / W;
    int w = r % W;                                      // multiple of 4 (W%4==0)

    const float* db = g_d + b * HW + h * W + w;
    float4 z = make_float4(0.f, 0.f, 0.f, 0.f);
    float4 d0 = (h > 0)      ? *reinterpret_cast<const float4*>(db - W) : z;
    float4 d1 =                *reinterpret_cast<const float4*>(db);
    float4 d2 = (h < H - 1)  ? *reinterpret_cast<const float4*>(db + W) : z;

    float* op = out + (size_t)b * C * HW + h * W + w;
    #pragma unroll
    for (int o = 0; o < C; o++) {
        float w0 = sw[o * 3 + 0], w1 = sw[o * 3 + 1], w2 = sw[o * 3 + 2];
        float4 rv;
        rv.x = w0 * d0.x + w1 * d1.x + w2 * d2.x;
        rv.y = w0 * d0.y + w1 * d1.y + w2 * d2.y;
        rv.z = w0 * d0.z + w1 * d1.z + w2 * d2.z;
        rv.w = w0 * d0.w + w1 * d1.w + w2 * d2.w;
        *reinterpret_cast<float4*>(op + (size_t)o * HW) = rv;
    }
}

extern "C" void kernel_launch(void* const* d_in, const int* in_sizes, int n_in,
                              void* d_out, int out_size) {
    const float* x  = (const float*)d_in[0];   // (4,32,720,720)
    const float* cw = (const float*)d_in[1];   // (32,32,3,1)
    float* out = (float*)d_out;                // (4,32,720,720)

    k_wsum<<<1, 96>>>(cw);

    {
        int n = BHW / 4;
        int thr = 256;
        k_csum<<<(n + thr - 1) / thr, thr>>>(x);
    }
    {
        int n = BHW;
        int thr = 256;
        k_diag<<<(n + thr - 1) / thr, thr>>>();
    }
    {
        int n = BHW / 4;
        int thr = 256;
        k_conv<<<(n + thr - 1) / thr, thr>>>(out);
    }
}

// round 3
// speedup vs baseline: 1.0184x; 1.0184x over previous
#include <cuda_runtime.h>
#include <cuda_bf16.h>

// Problem constants
constexpr int B = 4, C = 32, H = 720, W = 720;
constexpr int HW = H * W;              // 518400
constexpr int BHW = B * HW;            // 2073600

// Tiling for fused diag+conv kernel
constexpr int TH  = 8;     // output rows per block
constexpr int TWF = 360;   // output cols per block (W/2)
constexpr int SROWS = TH + 10;   // 18 s rows (halo ±5: d needs ±1 rows, each d row needs ±4)
constexpr int DROWS = TH + 2;    // 10 d rows
constexpr int SW  = 368;   // smem row width (360 + 8 halo cols), multiple of 4

// Scratch (no cudaMalloc allowed)
__device__ float g_s[BHW];       // channel sum
__device__ float g_w2[C * 3];    // collapsed weights

// K0: W2[o,kh] = sum_i conv_w[o,i,kh,0]
__global__ void k_wsum(const float* __restrict__ cw) {
    int t = threadIdx.x;
    if (t >= C * 3) return;
    int o = t / 3, kh = t % 3;
    float acc = 0.f;
    #pragma unroll
    for (int i = 0; i < C; i++) acc += cw[o * (C * 3) + i * 3 + kh];
    g_w2[t] = acc;
}

// K1: s[b,h,w] = sum_c x[b,c,h,w]  (float4 over w, streaming loads)
__global__ __launch_bounds__(256) void k_csum(const float* __restrict__ x) {
    int idx = blockIdx.x * blockDim.x + threadIdx.x;   // over BHW/4
    if (idx >= BHW / 4) return;
    int base = idx * 4;
    int b = base / HW;
    int hw = base % HW;
    const float4* xp = reinterpret_cast<const float4*>(x + (size_t)b * C * HW + hw);
    float4 acc = make_float4(0.f, 0.f, 0.f, 0.f);
    #pragma unroll
    for (int c = 0; c < C; c++) {
        float4 v = __ldcs(&xp[(size_t)c * (HW / 4)]);   // evict-first: x has no reuse
        acc.x += v.x; acc.y += v.y; acc.z += v.z; acc.w += v.w;
    }
    reinterpret_cast<float4*>(g_s)[idx] = acc;
}

// K2 (fused): d = 9-tap diagonal average of s (zero-padded), then
// out[b,o,h,w] = sum_kh W2[o,kh] * d[b, h-1+kh, w] (zero-padded in h)
__global__ __launch_bounds__(256) void k_fused(float* __restrict__ out) {
    __shared__ __align__(16) float s_sm[SROWS][SW];
    __shared__ __align__(16) float d_sm[DROWS][SW];
    __shared__ float sw[C * 3];

    int tid = threadIdx.x;
    if (tid < C * 3) sw[tid] = g_w2[tid];

    int b  = blockIdx.z;
    int h0 = blockIdx.y * TH;
    int w0 = blockIdx.x * TWF;
    const float* sb = g_s + b * HW;

    // Stage 1: load s tile [h0-5 .. h0+TH+4] x [w0-4 .. w0+TWF+3] into smem (zero pad OOB)
    // 18 rows x 92 float4
    for (int t = tid; t < SROWS * (SW / 4); t += 256) {
        int i = t / (SW / 4);
        int v = t % (SW / 4);
        int gr = h0 - 5 + i;
        int gc = w0 - 4 + 4 * v;       // either fully in-range or fully OOB (w0 mult of 360)
        float4 val = make_float4(0.f, 0.f, 0.f, 0.f);
        if (gr >= 0 && gr < H && gc >= 0 && gc + 3 < W)
            val = *reinterpret_cast<const float4*>(sb + gr * W + gc);
        *reinterpret_cast<float4*>(&s_sm[i][4 * v]) = val;
    }
    __syncthreads();

    // Stage 2: compute d tile rows r = h0-1 .. h0+TH (zero if r outside image)
    // d_sm[k][cc] corresponds to d[h0-1+k][w0+cc]
    for (int t = tid; t < DROWS * TWF; t += 256) {
        int k  = t / TWF;
        int cc = t % TWF;
        int r = h0 - 1 + k;
        float acc = 0.f;
        if (r >= 0 && r < H) {
            #pragma unroll
            for (int j = 0; j < 9; j++) acc += s_sm[k + j][cc + j];
            acc *= (1.0f / 9.0f);
        }
        d_sm[k][cc] = acc;
    }
    __syncthreads();

    // Stage 3: out. TH x (TWF/4) float4 positions per block
    for (int t = tid; t < TH * (TWF / 4); t += 256) {
        int k2 = t / (TWF / 4);
        int cf = t % (TWF / 4);
        int h  = h0 + k2;
        int wc = w0 + 4 * cf;

        float4 d0 = *reinterpret_cast<const float4*>(&d_sm[k2    ][4 * cf]);
        float4 d1 = *reinterpret_cast<const float4*>(&d_sm[k2 + 1][4 * cf]);
        float4 d2 = *reinterpret_cast<const float4*>(&d_sm[k2 + 2][4 * cf]);

        float* op = out + (size_t)b * C * HW + h * W + wc;
        #pragma unroll
        for (int o = 0; o < C; o++) {
            float a0 = sw[3 * o], a1 = sw[3 * o + 1], a2 = sw[3 * o + 2];
            float4 rv;
            rv.x = a0 * d0.x + a1 * d1.x + a2 * d2.x;
            rv.y = a0 * d0.y + a1 * d1.y + a2 * d2.y;
            rv.z = a0 * d0.z + a1 * d1.z + a2 * d2.z;
            rv.w = a0 * d0.w + a1 * d1.w + a2 * d2.w;
            *reinterpret_cast<float4*>(op + (size_t)o * HW) = rv;
        }
    }
}

extern "C" void kernel_launch(void* const* d_in, const int* in_sizes, int n_in,
                              void* d_out, int out_size) {
    const float* x  = (const float*)d_in[0];   // (4,32,720,720)
    const float* cw = (const float*)d_in[1];   // (32,32,3,1)
    float* out = (float*)d_out;                // (4,32,720,720)

    k_wsum<<<1, 96>>>(cw);

    {
        int n = BHW / 4;
        k_csum<<<(n + 255) / 256, 256>>>(x);
    }

    dim3 grid(W / TWF, H / TH, B);             // (2, 90, 4)
    k_fused<<<grid, 256>>>(out);
}

// round 4
// speedup vs baseline: 1.0928x; 1.0731x over previous
#include <cuda_runtime.h>
#include <cuda_bf16.h>

// Problem constants
constexpr int B = 4, C = 32, H = 720, W = 720;
constexpr int HW = H * W;              // 518400
constexpr int BHW = B * HW;            // 2073600

// Tiling for fused diag+conv kernel
constexpr int TH  = 8;     // output rows per block
constexpr int TWF = 360;   // output cols per block (W/2)
constexpr int SROWS = TH + 10;   // 18 s rows (halo: d needs ±1 rows, each d row ±4)
constexpr int DROWS = TH + 2;    // 10 d rows
constexpr int SW  = 368;   // smem row width (360 + 8 halo cols)

// Scratch (no cudaMalloc allowed)
__device__ float g_s[BHW];       // channel sum

// K1: s[b,h,w] = sum_c x[b,c,h,w]  (float4 over w, streaming loads)
__global__ __launch_bounds__(256) void k_csum(const float* __restrict__ x) {
    int idx = blockIdx.x * blockDim.x + threadIdx.x;   // over BHW/4
    if (idx >= BHW / 4) return;
    int base = idx * 4;
    int b = base / HW;
    int hw = base % HW;
    const float4* xp = reinterpret_cast<const float4*>(x + (size_t)b * C * HW + hw);
    float4 acc = make_float4(0.f, 0.f, 0.f, 0.f);
    #pragma unroll
    for (int c = 0; c < C; c++) {
        float4 v = __ldcs(&xp[(size_t)c * (HW / 4)]);   // evict-first: x has no reuse
        acc.x += v.x; acc.y += v.y; acc.z += v.z; acc.w += v.w;
    }
    reinterpret_cast<float4*>(g_s)[idx] = acc;          // keep s resident in L2
}

// K2 (fused): w2 reduction + 9-tap diagonal average of s + 3-tap broadcast conv
__global__ __launch_bounds__(256) void k_fused(const float* __restrict__ cw,
                                               float* __restrict__ out) {
    __shared__ __align__(16) float s_sm[SROWS][SW];
    __shared__ __align__(16) float d_sm[DROWS][SW];
    __shared__ float sw[C * 3];

    int tid = threadIdx.x;
    // Per-block w2 reduction: w2[o,kh] = sum_i conv_w[o,i,kh,0]  (L2-hit reads)
    if (tid < C * 3) {
        int o = tid / 3, kh = tid % 3;
        float acc = 0.f;
        #pragma unroll
        for (int i = 0; i < C; i++) acc += __ldg(&cw[o * (C * 3) + i * 3 + kh]);
        sw[tid] = acc;
    }

    int b  = blockIdx.z;
    int h0 = blockIdx.y * TH;
    int w0 = blockIdx.x * TWF;
    const float* sb = g_s + b * HW;

    // Stage 1: load s tile [h0-5 .. h0+TH+4] x [w0-4 .. w0+TWF+3] (zero pad OOB)
    for (int t = tid; t < SROWS * (SW / 4); t += 256) {
        int i = t / (SW / 4);
        int v = t % (SW / 4);
        int gr = h0 - 5 + i;
        int gc = w0 - 4 + 4 * v;
        float4 val = make_float4(0.f, 0.f, 0.f, 0.f);
        if (gr >= 0 && gr < H && gc >= 0 && gc + 3 < W)
            val = *reinterpret_cast<const float4*>(sb + gr * W + gc);
        *reinterpret_cast<float4*>(&s_sm[i][4 * v]) = val;
    }
    __syncthreads();

    // Stage 2: d tile rows r = h0-1 .. h0+TH (zero if r outside image)
    for (int t = tid; t < DROWS * TWF; t += 256) {
        int k  = t / TWF;
        int cc = t % TWF;
        int r = h0 - 1 + k;
        float acc = 0.f;
        if (r >= 0 && r < H) {
            #pragma unroll
            for (int j = 0; j < 9; j++) acc += s_sm[k + j][cc + j];
            acc *= (1.0f / 9.0f);
        }
        d_sm[k][cc] = acc;
    }
    __syncthreads();

    // Stage 3: out[b,o,h,w] = sum_kh w2[o,kh] * d[h-1+kh, w], streaming stores
    for (int t = tid; t < TH * (TWF / 4); t += 256) {
        int k2 = t / (TWF / 4);
        int cf = t % (TWF / 4);
        int h  = h0 + k2;
        int wc = w0 + 4 * cf;

        float4 d0 = *reinterpret_cast<const float4*>(&d_sm[k2    ][4 * cf]);
        float4 d1 = *reinterpret_cast<const float4*>(&d_sm[k2 + 1][4 * cf]);
        float4 d2 = *reinterpret_cast<const float4*>(&d_sm[k2 + 2][4 * cf]);

        float* op = out + (size_t)b * C * HW + h * W + wc;
        #pragma unroll
        for (int o = 0; o < C; o++) {
            float a0 = sw[3 * o], a1 = sw[3 * o + 1], a2 = sw[3 * o + 2];
            float4 rv;
            rv.x = a0 * d0.x + a1 * d1.x + a2 * d2.x;
            rv.y = a0 * d0.y + a1 * d1.y + a2 * d2.y;
            rv.z = a0 * d0.z + a1 * d1.z + a2 * d2.z;
            rv.w = a0 * d0.w + a1 * d1.w + a2 * d2.w;
            __stcs(reinterpret_cast<float4*>(op + (size_t)o * HW), rv);  // evict-first
        }
    }
}

extern "C" void kernel_launch(void* const* d_in, const int* in_sizes, int n_in,
                              void* d_out, int out_size) {
    const float* x  = (const float*)d_in[0];   // (4,32,720,720)
    const float* cw = (const float*)d_in[1];   // (32,32,3,1)
    float* out = (float*)d_out;                // (4,32,720,720)

    {
        int n = BHW / 4;
        k_csum<<<(n + 255) / 256, 256>>>(x);
    }

    dim3 grid(W / TWF, H / TH, B);             // (2, 90, 4)
    k_fused<<<grid, 256>>>(cw, out);
}

// round 5
// speedup vs baseline: 1.1137x; 1.0191x over previous
#include <cuda_runtime.h>
#include <cuda_bf16.h>

// Problem constants
constexpr int B = 4, C = 32, H = 720, W = 720;
constexpr int HW = H * W;              // 518400
constexpr int BHW = B * HW;            // 2073600

// Tiling for fused diag+conv kernel
constexpr int TH  = 8;     // output rows per block
constexpr int TWF = 360;   // output cols per block (W/2)
constexpr int SROWS = TH + 10;   // 18 s rows (halo: d needs ±1 rows, each d row ±4)
constexpr int DROWS = TH + 2;    // 10 d rows
constexpr int SW  = 368;   // smem row width (360 + 8 halo cols)

// Scratch (no cudaMalloc allowed)
__device__ float g_s[BHW];       // channel sum

// K1: s[b,h,w] = sum_c x[b,c,h,w]  (float4 over w, streaming loads)
__global__ __launch_bounds__(256) void k_csum(const float* __restrict__ x) {
    int idx = blockIdx.x * blockDim.x + threadIdx.x;   // over BHW/4
    if (idx >= BHW / 4) return;
    int base = idx * 4;
    int b = base / HW;
    int hw = base % HW;
    const float4* xp = reinterpret_cast<const float4*>(x + (size_t)b * C * HW + hw);
    float4 acc = make_float4(0.f, 0.f, 0.f, 0.f);
    #pragma unroll
    for (int c = 0; c < C; c++) {
        float4 v = __ldcs(&xp[(size_t)c * (HW / 4)]);   // evict-first: x has no reuse
        acc.x += v.x; acc.y += v.y; acc.z += v.z; acc.w += v.w;
    }
    reinterpret_cast<float4*>(g_s)[idx] = acc;          // keep s resident in L2
}

// K2 (fused): w2 reduction + 9-tap diagonal average of s + 3-tap broadcast conv
__global__ __launch_bounds__(256) void k_fused(const float* __restrict__ cw,
                                               float* __restrict__ out) {
    __shared__ __align__(16) float s_sm[SROWS][SW];
    __shared__ __align__(16) float d_sm[DROWS][SW];
    __shared__ float sw[C * 3];

    int tid = threadIdx.x;
    // Per-block w2 reduction: w2[o,kh] = sum_i conv_w[o,i,kh,0]  (L2-hit reads)
    if (tid < C * 3) {
        int o = tid / 3, kh = tid % 3;
        float acc = 0.f;
        #pragma unroll
        for (int i = 0; i < C; i++) acc += __ldg(&cw[o * (C * 3) + i * 3 + kh]);
        sw[tid] = acc;
    }

    int b  = blockIdx.z;
    int h0 = blockIdx.y * TH;
    int w0 = blockIdx.x * TWF;
    const float* sb = g_s + b * HW;

    // Stage 1: load s tile [h0-5 .. h0+TH+4] x [w0-4 .. w0+TWF+3] (zero pad OOB)
    for (int t = tid; t < SROWS * (SW / 4); t += 256) {
        int i = t / (SW / 4);
        int v = t % (SW / 4);
        int gr = h0 - 5 + i;
        int gc = w0 - 4 + 4 * v;
        float4 val = make_float4(0.f, 0.f, 0.f, 0.f);
        if (gr >= 0 && gr < H && gc >= 0 && gc + 3 < W)
            val = *reinterpret_cast<const float4*>(sb + gr * W + gc);
        *reinterpret_cast<float4*>(&s_sm[i][4 * v]) = val;
    }
    __syncthreads();

    // Stage 2: d tile rows r = h0-1 .. h0+TH (zero if r outside image)
    for (int t = tid; t < DROWS * TWF; t += 256) {
        int k  = t / TWF;
        int cc = t % TWF;
        int r = h0 - 1 + k;
        float acc = 0.f;
        if (r >= 0 && r < H) {
            #pragma unroll
            for (int j = 0; j < 9; j++) acc += s_sm[k + j][cc + j];
            acc *= (1.0f / 9.0f);
        }
        d_sm[k][cc] = acc;
    }
    __syncthreads();

    // Stage 3: out[b,o,h,w] = sum_kh w2[o,kh] * d[h-1+kh, w], streaming stores
    for (int t = tid; t < TH * (TWF / 4); t += 256) {
        int k2 = t / (TWF / 4);
        int cf = t % (TWF / 4);
        int h  = h0 + k2;
        int wc = w0 + 4 * cf;

        float4 d0 = *reinterpret_cast<const float4*>(&d_sm[k2    ][4 * cf]);
        float4 d1 = *reinterpret_cast<const float4*>(&d_sm[k2 + 1][4 * cf]);
        float4 d2 = *reinterpret_cast<const float4*>(&d_sm[k2 + 2][4 * cf]);

        float* op = out + (size_t)b * C * HW + h * W + wc;
        #pragma unroll
        for (int o = 0; o < C; o++) {
            float a0 = sw[3 * o], a1 = sw[3 * o + 1], a2 = sw[3 * o + 2];
            float4 rv;
            rv.x = a0 * d0.x + a1 * d1.x + a2 * d2.x;
            rv.y = a0 * d0.y + a1 * d1.y + a2 * d2.y;
            rv.z = a0 * d0.z + a1 * d1.z + a2 * d2.z;
            rv.w = a0 * d0.w + a1 * d1.w + a2 * d2.w;
            __stcs(reinterpret_cast<float4*>(op + (size_t)o * HW), rv);  // evict-first
        }
    }
}

extern "C" void kernel_launch(void* const* d_in, const int* in_sizes, int n_in,
                              void* d_out, int out_size) {
    const float* x  = (const float*)d_in[0];   // (4,32,720,720)
    const float* cw = (const float*)d_in[1];   // (32,32,3,1)
    float* out = (float*)d_out;                // (4,32,720,720)

    {
        int n = BHW / 4;
        k_csum<<<(n + 255) / 256, 256>>>(x);
    }

    dim3 grid(W / TWF, H / TH, B);             // (2, 90, 4)
    k_fused<<<grid, 256>>>(cw, out);
}